// round 12
// baseline (speedup 1.0000x reference)
#include <cuda_runtime.h>
#include <cuda_bf16.h>

// CRF forward scan, probability domain, tensor-pipe matvec.
// mma.sync.m16n8k16 (bf16 x bf16 -> f32); warp w owns states [32w, 32w+32);
// all 8 B-columns carry the same state vector (broadcast trick).
// R12: (1) PERMUTED smem state layout: u32 word w stored at (w&3)*16+(w>>2)
//      -> each lane's 16 B-frag words are contiguous: 4x LDS.128 not 16x LDS.32.
//      (2) HMMA accumulate chains split depth 4 -> 2 (8 chains of 2).
// Everything else: R11 champion (every-step REDUX power-of-two renorm,
// unroll x2 static buffers, 3-deep y prefetch, one __syncthreads/step).

#define KDIM 128

__device__ __forceinline__ unsigned bpack(float lo, float hi) {
    unsigned r;
    asm("cvt.rn.bf16x2.f32 %0, %1, %2;" : "=r"(r) : "f"(hi), "f"(lo));
    return r;
}

#define MMA(C, A, Bv)                                                        \
    asm volatile(                                                            \
        "mma.sync.aligned.m16n8k16.row.col.f32.bf16.bf16.f32 "               \
        "{%0,%1,%2,%3},{%4,%5,%6,%7},{%8,%9},{%0,%1,%2,%3};"                 \
        : "+f"(C[0]), "+f"(C[1]), "+f"(C[2]), "+f"(C[3])                     \
        : "r"(A[0]), "r"(A[1]), "r"(A[2]), "r"(A[3]),                        \
          "r"(Bv[0]), "r"(Bv[1]))

__global__ __launch_bounds__(128, 1)
void crf_fwd_kernel(const float* __restrict__ y,
                    const float* __restrict__ mask,
                    const float* __restrict__ trans,
                    float* __restrict__ out,
                    int T) {
    const int b    = blockIdx.x;
    const int tid  = threadIdx.x;
    const int lane = tid & 31;
    const int warp = tid >> 5;          // 0..3 : states [32w, 32w+32)
    const int g4   = lane >> 2;         // 0..7
    const int tig  = lane & 3;          // 0..3

    // permuted state buffers: u32 word w lives at position (w&3)*16 + (w>>2)
    __shared__ __align__(16) unsigned shp[2][64];
    __shared__ __align__(16) unsigned wmax[2][4];
    __shared__ float redf[4];
    __shared__ int   len_sh;

    // ---- one-time: E = exp(trans) as mma A-fragments (bf16), 64 regs ----
    unsigned EA[2][8][4];
    #pragma unroll
    for (int mt = 0; mt < 2; mt++) {
        const int r0 = 32 * warp + 16 * mt + g4;
        const float* tr0 = trans + (size_t)r0 * KDIM;
        const float* tr1 = tr0 + 8 * KDIM;
        #pragma unroll
        for (int kt = 0; kt < 8; kt++) {
            const int c0 = 16 * kt + 2 * tig;
            EA[mt][kt][0] = bpack(expf(tr0[c0]),   expf(tr0[c0+1]));
            EA[mt][kt][1] = bpack(expf(tr1[c0]),   expf(tr1[c0+1]));
            EA[mt][kt][2] = bpack(expf(tr0[c0+8]), expf(tr0[c0+9]));
            EA[mt][kt][3] = bpack(expf(tr1[c0+8]), expf(tr1[c0+9]));
        }
    }

    // ---- init state (permuted), renorm buffers, length ----
    if (tid == 0) len_sh = 0;
    if (tid < KDIM) {
        int w = tid >> 1;
        int p = ((w & 3) << 4) + (w >> 2);
        reinterpret_cast<__nv_bfloat16*>(shp[0])[2 * p + (tid & 1)] =
            __float2bfloat16_rn((tid == 2) ? 1.0f : 0.0f);   // SOS_IDX = 2
    }
    if (tid < 8) wmax[tid >> 2][tid & 3] = 0x3f800000u;      // both slots 1.0
    __syncthreads();
    {
        const float* mb = mask + (size_t)b * T;
        int cnt = 0;
        for (int t = tid; t < T; t += KDIM) cnt += (mb[t] != 0.0f);
        cnt = __reduce_add_sync(0xffffffffu, cnt);
        if (lane == 0) atomicAdd(&len_sh, cnt);
    }
    __syncthreads();
    const int len = len_sh;

    // ---- y prefetch pipeline (3 deep); thread owns states m0+{0,8,16,24} ----
    const int m0 = 32 * warp + g4;
    const float* yb   = y + (size_t)b * T * KDIM + m0;
    const float* yp   = yb + 3 * KDIM;
    const float* yend = yb + (size_t)T * KDIM;
    float ey[4], yA[4], yB[4];
    #pragma unroll
    for (int k = 0; k < 4; k++) {
        ey[k] = (len > 0) ? __expf(yb[8 * k]) : 1.0f;
        yA[k] = (1 < T) ? yb[KDIM + 8 * k]     : 0.0f;
        yB[k] = (2 < T) ? yb[2 * KDIM + 8 * k] : 0.0f;
    }

    // store-side permuted addressing for this lane:
    // state e = m0 + 8k -> w = 16*warp + 4k + (g4>>1), p = (g4>>1)*16 + 4*warp + k
    const int pbase = ((g4 >> 1) << 4) + (warp << 2);
    const int poff  = g4 & 1;

    float s0 = (warp == 0 && g4 == 2) ? 1.0f : 0.0f;   // for final reduce
    float s1 = 0.0f, s2 = 0.0f, s3 = 0.0f;
    int eacc = 0;

#define STEP(SRC, DST)                                                       \
    {                                                                        \
        /* 4x LDS.128: lane tig's 16 contiguous B-frag words */              \
        const uint4* sp4 = reinterpret_cast<const uint4*>(shp[SRC]) + (tig << 2); \
        uint4 q0 = sp4[0], q1 = sp4[1], q2 = sp4[2], q3 = sp4[3];            \
        uint4 wm4 = *reinterpret_cast<const uint4*>(wmax[SRC]);              \
        unsigned mbits = max(max(wm4.x, wm4.y), max(wm4.z, wm4.w));          \
        int Ee   = (int)(mbits >> 23);                                       \
        float rz = __uint_as_float((unsigned)(254 - Ee) << 23);              \
        eacc    += Ee - 127;                                                 \
        float ez0 = ey[0]*rz, ez1 = ey[1]*rz, ez2 = ey[2]*rz, ez3 = ey[3]*rz;\
        unsigned rb[8][2] = {{q0.x,q0.y},{q0.z,q0.w},{q1.x,q1.y},{q1.z,q1.w},\
                             {q2.x,q2.y},{q2.z,q2.w},{q3.x,q3.y},{q3.z,q3.w}};\
        /* 8 accumulate chains of depth 2 (4 per mt) */                      \
        float cA0[4]={0,0,0,0}, cB0[4]={0,0,0,0}, cC0[4]={0,0,0,0}, cD0[4]={0,0,0,0}; \
        float cA1[4]={0,0,0,0}, cB1[4]={0,0,0,0}, cC1[4]={0,0,0,0}, cD1[4]={0,0,0,0}; \
        MMA(cA0, EA[0][0], rb[0]);  MMA(cA1, EA[1][0], rb[0]);               \
        MMA(cB0, EA[0][2], rb[2]);  MMA(cB1, EA[1][2], rb[2]);               \
        MMA(cC0, EA[0][4], rb[4]);  MMA(cC1, EA[1][4], rb[4]);               \
        MMA(cD0, EA[0][6], rb[6]);  MMA(cD1, EA[1][6], rb[6]);               \
        MMA(cA0, EA[0][1], rb[1]);  MMA(cA1, EA[1][1], rb[1]);               \
        MMA(cB0, EA[0][3], rb[3]);  MMA(cB1, EA[1][3], rb[3]);               \
        MMA(cC0, EA[0][5], rb[5]);  MMA(cC1, EA[1][5], rb[5]);               \
        MMA(cD0, EA[0][7], rb[7]);  MMA(cD1, EA[1][7], rb[7]);               \
        s0 = ((cA0[0]+cB0[0]) + (cC0[0]+cD0[0])) * ez0;  /* m0      */       \
        s1 = ((cA0[2]+cB0[2]) + (cC0[2]+cD0[2])) * ez1;  /* m0 + 8  */       \
        s2 = ((cA1[0]+cB1[0]) + (cC1[0]+cD1[0])) * ez2;  /* m0 + 16 */       \
        s3 = ((cA1[2]+cB1[2]) + (cC1[2]+cD1[2])) * ez3;  /* m0 + 24 */       \
        __nv_bfloat16* sd = reinterpret_cast<__nv_bfloat16*>(shp[DST]);      \
        sd[2*(pbase+0)+poff] = __float2bfloat16_rn(s0);                      \
        sd[2*(pbase+1)+poff] = __float2bfloat16_rn(s1);                      \
        sd[2*(pbase+2)+poff] = __float2bfloat16_rn(s2);                      \
        sd[2*(pbase+3)+poff] = __float2bfloat16_rn(s3);                      \
        unsigned mm = max(max(__float_as_uint(s0), __float_as_uint(s1)),     \
                          max(__float_as_uint(s2), __float_as_uint(s3)));    \
        mm = __reduce_max_sync(0xffffffffu, mm);                             \
        if (lane == 0) wmax[DST][warp] = mm;                                 \
        _Pragma("unroll")                                                    \
        for (int k = 0; k < 4; k++) {                                        \
            ey[k] = __expf(yA[k]);                                           \
            yA[k] = yB[k];                                                   \
            yB[k] = (yp < yend) ? yp[8 * k] : 0.0f;                          \
        }                                                                    \
        yp += KDIM;                                                          \
        __syncthreads();                                                     \
    }

    const int len2 = len & ~1;
    for (int t = 0; t < len2; t += 2) {
        STEP(0, 1)
        STEP(1, 0)
    }
    if (len & 1) {
        STEP(0, 1)
    }
#undef STEP

    // ---- final: out[b] = log(sum_i s_i) + eacc*ln2 ----
    // each state held by 4 lanes (tig duplicates) -> warp sum = 4x partial
    float e = (s0 + s1) + (s2 + s3);
    e += __shfl_xor_sync(0xffffffffu, e, 16);
    e += __shfl_xor_sync(0xffffffffu, e, 8);
    e += __shfl_xor_sync(0xffffffffu, e, 4);
    e += __shfl_xor_sync(0xffffffffu, e, 2);
    e += __shfl_xor_sync(0xffffffffu, e, 1);
    if (lane == 0) redf[warp] = e;
    __syncthreads();
    if (tid == 0) {
        float tot = ((redf[0] + redf[1]) + (redf[2] + redf[3])) * 0.25f;
        out[b] = logf(tot) + (float)((double)eacc * 0.6931471805599453);
    }
}

extern "C" void kernel_launch(void* const* d_in, const int* in_sizes, int n_in,
                              void* d_out, int out_size) {
    const float* y     = (const float*)d_in[0];   // (B, T, K) f32
    const float* mask  = (const float*)d_in[1];   // (B, T)    f32
    const float* trans = (const float*)d_in[2];   // (K, K)    f32
    float* out = (float*)d_out;                   // (B,)      f32

    const int B = out_size;                       // 64
    const int T = in_sizes[1] / B;                // 256

    crf_fwd_kernel<<<B, 128>>>(y, mask, trans, out, T);
}

// round 13
// speedup vs baseline: 1.1707x; 1.1707x over previous
#include <cuda_runtime.h>
#include <cuda_bf16.h>

// CRF forward scan, probability domain, tensor-pipe matvec.
// mma.sync.m16n8k16 (bf16 x bf16 -> f32); warp w owns states [32w, 32w+32);
// all 8 B-columns carry the same state vector (broadcast trick).
// R13 = R11 champion (45.8us) with ONE change: HMMA accumulate chains split
// from depth 4 (4 chains) to depth 2 (8 chains) to shorten the serial
// tensor-op spine. Everything else identical: 16x broadcast LDS.32 B-frags,
// every-step REDUX power-of-two renorm, unroll x2 static buffers, 3-deep
// y prefetch, one __syncthreads per step.

#define KDIM 128

__device__ __forceinline__ unsigned bpack(float lo, float hi) {
    unsigned r;
    asm("cvt.rn.bf16x2.f32 %0, %1, %2;" : "=r"(r) : "f"(hi), "f"(lo));
    return r;
}

#define MMA(C, A, Bv)                                                        \
    asm volatile(                                                            \
        "mma.sync.aligned.m16n8k16.row.col.f32.bf16.bf16.f32 "               \
        "{%0,%1,%2,%3},{%4,%5,%6,%7},{%8,%9},{%0,%1,%2,%3};"                 \
        : "+f"(C[0]), "+f"(C[1]), "+f"(C[2]), "+f"(C[3])                     \
        : "r"(A[0]), "r"(A[1]), "r"(A[2]), "r"(A[3]),                        \
          "r"(Bv[0]), "r"(Bv[1]))

__global__ __launch_bounds__(128, 1)
void crf_fwd_kernel(const float* __restrict__ y,
                    const float* __restrict__ mask,
                    const float* __restrict__ trans,
                    float* __restrict__ out,
                    int T) {
    const int b    = blockIdx.x;
    const int tid  = threadIdx.x;
    const int lane = tid & 31;
    const int warp = tid >> 5;          // 0..3 : states [32w, 32w+32)
    const int g4   = lane >> 2;         // 0..7
    const int tig  = lane & 3;          // 0..3

    __shared__ __align__(16) __nv_bfloat16 sh[2][KDIM];
    __shared__ __align__(16) unsigned wmax[2][4];
    __shared__ float redf[4];
    __shared__ int   len_sh;

    // ---- one-time: E = exp(trans) as mma A-fragments (bf16), 64 regs ----
    unsigned EA[2][8][4];
    #pragma unroll
    for (int mt = 0; mt < 2; mt++) {
        const int r0 = 32 * warp + 16 * mt + g4;
        const float* tr0 = trans + (size_t)r0 * KDIM;
        const float* tr1 = tr0 + 8 * KDIM;
        #pragma unroll
        for (int kt = 0; kt < 8; kt++) {
            const int c0 = 16 * kt + 2 * tig;
            EA[mt][kt][0] = bpack(expf(tr0[c0]),   expf(tr0[c0+1]));
            EA[mt][kt][1] = bpack(expf(tr1[c0]),   expf(tr1[c0+1]));
            EA[mt][kt][2] = bpack(expf(tr0[c0+8]), expf(tr0[c0+9]));
            EA[mt][kt][3] = bpack(expf(tr1[c0+8]), expf(tr1[c0+9]));
        }
    }

    // ---- init state, renorm buffers, length ----
    if (tid == 0) len_sh = 0;
    if (tid < KDIM) sh[0][tid] = __float2bfloat16_rn((tid == 2) ? 1.0f : 0.0f);
    if (tid < 8) wmax[tid >> 2][tid & 3] = 0x3f800000u;   // both slots = 1.0
    __syncthreads();
    {
        const float* mb = mask + (size_t)b * T;
        int cnt = 0;
        for (int t = tid; t < T; t += KDIM) cnt += (mb[t] != 0.0f);
        cnt = __reduce_add_sync(0xffffffffu, cnt);
        if (lane == 0) atomicAdd(&len_sh, cnt);
    }
    __syncthreads();
    const int len = len_sh;

    // ---- y prefetch pipeline (3 deep); thread owns 4 states: m0+{0,8,16,24}
    const int m0 = 32 * warp + g4;
    const float* yb   = y + (size_t)b * T * KDIM + m0;
    const float* yp   = yb + 3 * KDIM;
    const float* yend = yb + (size_t)T * KDIM;
    float ey[4], yA[4], yB[4];
    #pragma unroll
    for (int k = 0; k < 4; k++) {
        ey[k] = (len > 0) ? __expf(yb[8 * k]) : 1.0f;
        yA[k] = (1 < T) ? yb[KDIM + 8 * k]     : 0.0f;
        yB[k] = (2 < T) ? yb[2 * KDIM + 8 * k] : 0.0f;
    }

    // live state (fp32) for the 4 owned states (4x redundant per group)
    float s0 = (warp == 0 && g4 == 2) ? 1.0f : 0.0f;   // SOS_IDX = 2
    float s1 = 0.0f, s2 = 0.0f, s3 = 0.0f;
    int eacc = 0;

#define STEP(SRC, DST)                                                       \
    {                                                                        \
        uint4 wm4 = *reinterpret_cast<const uint4*>(wmax[SRC]);              \
        unsigned mbits = max(max(wm4.x, wm4.y), max(wm4.z, wm4.w));          \
        int Ee   = (int)(mbits >> 23);                                       \
        float rz = __uint_as_float((unsigned)(254 - Ee) << 23);              \
        eacc    += Ee - 127;                                                 \
        float ez0 = ey[0]*rz, ez1 = ey[1]*rz, ez2 = ey[2]*rz, ez3 = ey[3]*rz;\
        /* B fragments: u32 idx = 8*kt + tig (rows 2tig,+1), +4 (rows +8,+9)*/\
        unsigned rb[8][2];                                                   \
        const unsigned* spb = reinterpret_cast<const unsigned*>(sh[SRC]) + tig;\
        _Pragma("unroll")                                                    \
        for (int kt = 0; kt < 8; kt++) {                                     \
            rb[kt][0] = spb[8 * kt];                                         \
            rb[kt][1] = spb[8 * kt + 4];                                     \
        }                                                                    \
        /* 8 accumulate chains of depth 2 (was 4 chains of depth 4) */       \
        float cA0[4]={0,0,0,0}, cB0[4]={0,0,0,0};                            \
        float cC0[4]={0,0,0,0}, cD0[4]={0,0,0,0};                            \
        float cA1[4]={0,0,0,0}, cB1[4]={0,0,0,0};                            \
        float cC1[4]={0,0,0,0}, cD1[4]={0,0,0,0};                            \
        MMA(cA0, EA[0][0], rb[0]);  MMA(cA1, EA[1][0], rb[0]);               \
        MMA(cB0, EA[0][2], rb[2]);  MMA(cB1, EA[1][2], rb[2]);               \
        MMA(cC0, EA[0][4], rb[4]);  MMA(cC1, EA[1][4], rb[4]);               \
        MMA(cD0, EA[0][6], rb[6]);  MMA(cD1, EA[1][6], rb[6]);               \
        MMA(cA0, EA[0][1], rb[1]);  MMA(cA1, EA[1][1], rb[1]);               \
        MMA(cB0, EA[0][3], rb[3]);  MMA(cB1, EA[1][3], rb[3]);               \
        MMA(cC0, EA[0][5], rb[5]);  MMA(cC1, EA[1][5], rb[5]);               \
        MMA(cD0, EA[0][7], rb[7]);  MMA(cD1, EA[1][7], rb[7]);               \
        s0 = ((cA0[0]+cB0[0]) + (cC0[0]+cD0[0])) * ez0;  /* m0      */       \
        s1 = ((cA0[2]+cB0[2]) + (cC0[2]+cD0[2])) * ez1;  /* m0 + 8  */       \
        s2 = ((cA1[0]+cB1[0]) + (cC1[0]+cD1[0])) * ez2;  /* m0 + 16 */       \
        s3 = ((cA1[2]+cB1[2]) + (cC1[2]+cD1[2])) * ez3;  /* m0 + 24 */       \
        __nv_bfloat16* sd = sh[DST] + m0;                                    \
        sd[0]  = __float2bfloat16_rn(s0);                                    \
        sd[8]  = __float2bfloat16_rn(s1);                                    \
        sd[16] = __float2bfloat16_rn(s2);                                    \
        sd[24] = __float2bfloat16_rn(s3);                                    \
        unsigned mm = max(max(__float_as_uint(s0), __float_as_uint(s1)),     \
                          max(__float_as_uint(s2), __float_as_uint(s3)));    \
        mm = __reduce_max_sync(0xffffffffu, mm);                             \
        if (lane == 0) wmax[DST][warp] = mm;                                 \
        _Pragma("unroll")                                                    \
        for (int k = 0; k < 4; k++) {                                        \
            ey[k] = __expf(yA[k]);                                           \
            yA[k] = yB[k];                                                   \
            yB[k] = (yp < yend) ? yp[8 * k] : 0.0f;                          \
        }                                                                    \
        yp += KDIM;                                                          \
        __syncthreads();                                                     \
    }

    const int len2 = len & ~1;
    for (int t = 0; t < len2; t += 2) {
        STEP(0, 1)
        STEP(1, 0)
    }
    if (len & 1) {
        STEP(0, 1)
    }
#undef STEP

    // ---- final: out[b] = log(sum_i s_i) + eacc*ln2 ----
    // each state held by 4 lanes -> warp sum = 4 * true partial sum
    float e = (s0 + s1) + (s2 + s3);
    e += __shfl_xor_sync(0xffffffffu, e, 16);
    e += __shfl_xor_sync(0xffffffffu, e, 8);
    e += __shfl_xor_sync(0xffffffffu, e, 4);
    e += __shfl_xor_sync(0xffffffffu, e, 2);
    e += __shfl_xor_sync(0xffffffffu, e, 1);
    if (lane == 0) redf[warp] = e;
    __syncthreads();
    if (tid == 0) {
        float tot = ((redf[0] + redf[1]) + (redf[2] + redf[3])) * 0.25f;
        out[b] = logf(tot) + (float)((double)eacc * 0.6931471805599453);
    }
}

extern "C" void kernel_launch(void* const* d_in, const int* in_sizes, int n_in,
                              void* d_out, int out_size) {
    const float* y     = (const float*)d_in[0];   // (B, T, K) f32
    const float* mask  = (const float*)d_in[1];   // (B, T)    f32
    const float* trans = (const float*)d_in[2];   // (K, K)    f32
    float* out = (float*)d_out;                   // (B,)      f32

    const int B = out_size;                       // 64
    const int T = in_sizes[1] / B;                // 256

    crf_fwd_kernel<<<B, 128>>>(y, mask, trans, out, T);
}

// round 14
// speedup vs baseline: 1.2242x; 1.0457x over previous
#include <cuda_runtime.h>
#include <cuda_bf16.h>

// CRF forward scan, probability domain, tensor-pipe matvec.
// mma.sync.m16n8k16 (bf16 x bf16 -> f32); warp w owns states [32w, 32w+32);
// all 8 B-columns carry the same state vector (broadcast trick).
// R14 = R11 champion with ONE change: conflict-free PERMUTED smem layout so
// each lane's 16 B-frag words load as 4x LDS.128 (was 16x LDS.32).
//   word w of the state vector stored at p(w) = (w>>4)*16 + (w&3)*4 + ((w>>2)&3)
//   lane tig reads uint4 indices {tig, 4+tig, 8+tig, 12+tig}:
//   per instruction banks {16q+4tig..+3} mod 32 -> 16 distinct banks, no conflicts.
// Depth-4 HMMA chains kept (R13 showed splitting hurts). Every-step REDUX
// power-of-two renorm, unroll x2 static buffers, 3-deep y prefetch.

#define KDIM 128

__device__ __forceinline__ unsigned bpack(float lo, float hi) {
    unsigned r;
    asm("cvt.rn.bf16x2.f32 %0, %1, %2;" : "=r"(r) : "f"(hi), "f"(lo));
    return r;
}

#define MMA(C, A, Bv)                                                        \
    asm volatile(                                                            \
        "mma.sync.aligned.m16n8k16.row.col.f32.bf16.bf16.f32 "               \
        "{%0,%1,%2,%3},{%4,%5,%6,%7},{%8,%9},{%0,%1,%2,%3};"                 \
        : "+f"(C[0]), "+f"(C[1]), "+f"(C[2]), "+f"(C[3])                     \
        : "r"(A[0]), "r"(A[1]), "r"(A[2]), "r"(A[3]),                        \
          "r"(Bv[0]), "r"(Bv[1]))

__global__ __launch_bounds__(128, 1)
void crf_fwd_kernel(const float* __restrict__ y,
                    const float* __restrict__ mask,
                    const float* __restrict__ trans,
                    float* __restrict__ out,
                    int T) {
    const int b    = blockIdx.x;
    const int tid  = threadIdx.x;
    const int lane = tid & 31;
    const int warp = tid >> 5;          // 0..3 : states [32w, 32w+32)
    const int g4   = lane >> 2;         // 0..7
    const int tig  = lane & 3;          // 0..3

    // permuted state buffers (64 u32 words = 128 bf16 each)
    __shared__ __align__(16) unsigned shp[2][64];
    __shared__ __align__(16) unsigned wmax[2][4];
    __shared__ float redf[4];
    __shared__ int   len_sh;

    // ---- one-time: E = exp(trans) as mma A-fragments (bf16), 64 regs ----
    unsigned EA[2][8][4];
    #pragma unroll
    for (int mt = 0; mt < 2; mt++) {
        const int r0 = 32 * warp + 16 * mt + g4;
        const float* tr0 = trans + (size_t)r0 * KDIM;
        const float* tr1 = tr0 + 8 * KDIM;
        #pragma unroll
        for (int kt = 0; kt < 8; kt++) {
            const int c0 = 16 * kt + 2 * tig;
            EA[mt][kt][0] = bpack(expf(tr0[c0]),   expf(tr0[c0+1]));
            EA[mt][kt][1] = bpack(expf(tr1[c0]),   expf(tr1[c0+1]));
            EA[mt][kt][2] = bpack(expf(tr0[c0+8]), expf(tr0[c0+9]));
            EA[mt][kt][3] = bpack(expf(tr1[c0+8]), expf(tr1[c0+9]));
        }
    }

    // ---- init state (permuted), renorm buffers, length ----
    if (tid == 0) len_sh = 0;
    if (tid < KDIM) {
        int w = tid >> 1;
        int p = ((w >> 4) << 4) + ((w & 3) << 2) + ((w >> 2) & 3);
        reinterpret_cast<__nv_bfloat16*>(shp[0])[2 * p + (tid & 1)] =
            __float2bfloat16_rn((tid == 2) ? 1.0f : 0.0f);   // SOS_IDX = 2
    }
    if (tid < 8) wmax[tid >> 2][tid & 3] = 0x3f800000u;      // both slots 1.0
    __syncthreads();
    {
        const float* mb = mask + (size_t)b * T;
        int cnt = 0;
        for (int t = tid; t < T; t += KDIM) cnt += (mb[t] != 0.0f);
        cnt = __reduce_add_sync(0xffffffffu, cnt);
        if (lane == 0) atomicAdd(&len_sh, cnt);
    }
    __syncthreads();
    const int len = len_sh;

    // ---- y prefetch pipeline (3 deep); thread owns states m0+{0,8,16,24} ----
    const int m0 = 32 * warp + g4;
    const float* yb   = y + (size_t)b * T * KDIM + m0;
    const float* yp   = yb + 3 * KDIM;
    const float* yend = yb + (size_t)T * KDIM;
    float ey[4], yA[4], yB[4];
    #pragma unroll
    for (int k = 0; k < 4; k++) {
        ey[k] = (len > 0) ? __expf(yb[8 * k]) : 1.0f;
        yA[k] = (1 < T) ? yb[KDIM + 8 * k]     : 0.0f;
        yB[k] = (2 < T) ? yb[2 * KDIM + 8 * k] : 0.0f;
    }

    // store-side permuted base: state 32w+8k+g4 -> bf16 idx
    //   32*warp + 8*(g4>>1) + 2k + (g4&1)
    const int sbase = 32 * warp + ((g4 >> 1) << 3) + (g4 & 1);

    float s0 = (warp == 0 && g4 == 2) ? 1.0f : 0.0f;   // for final reduce
    float s1 = 0.0f, s2 = 0.0f, s3 = 0.0f;
    int eacc = 0;

#define STEP(SRC, DST)                                                       \
    {                                                                        \
        /* 4x LDS.128 first: latency overlaps the renorm math below */       \
        const uint4* sp4 = reinterpret_cast<const uint4*>(shp[SRC]);         \
        uint4 q0 = sp4[tig], q1 = sp4[4 + tig];                              \
        uint4 q2 = sp4[8 + tig], q3 = sp4[12 + tig];                         \
        uint4 wm4 = *reinterpret_cast<const uint4*>(wmax[SRC]);              \
        unsigned mbits = max(max(wm4.x, wm4.y), max(wm4.z, wm4.w));          \
        int Ee   = (int)(mbits >> 23);                                       \
        float rz = __uint_as_float((unsigned)(254 - Ee) << 23);              \
        eacc    += Ee - 127;                                                 \
        float ez0 = ey[0]*rz, ez1 = ey[1]*rz, ez2 = ey[2]*rz, ez3 = ey[3]*rz;\
        /* chunk q = {rb[2q][0], rb[2q][1], rb[2q+1][0], rb[2q+1][1]} */     \
        unsigned rb[8][2] = {{q0.x,q0.y},{q0.z,q0.w},{q1.x,q1.y},{q1.z,q1.w},\
                             {q2.x,q2.y},{q2.z,q2.w},{q3.x,q3.y},{q3.z,q3.w}};\
        /* 4 accumulate chains of depth 4 (champion config) */               \
        float cP0[4] = {0,0,0,0}, cQ0[4] = {0,0,0,0};                        \
        float cP1[4] = {0,0,0,0}, cQ1[4] = {0,0,0,0};                        \
        _Pragma("unroll")                                                    \
        for (int kp = 0; kp < 4; kp++) {                                     \
            MMA(cP0, EA[0][2*kp],   rb[2*kp]);                               \
            MMA(cP1, EA[1][2*kp],   rb[2*kp]);                               \
            MMA(cQ0, EA[0][2*kp+1], rb[2*kp+1]);                             \
            MMA(cQ1, EA[1][2*kp+1], rb[2*kp+1]);                             \
        }                                                                    \
        s0 = (cP0[0] + cQ0[0]) * ez0;   /* state m0      */                  \
        s1 = (cP0[2] + cQ0[2]) * ez1;   /* state m0 + 8  */                  \
        s2 = (cP1[0] + cQ1[0]) * ez2;   /* state m0 + 16 */                  \
        s3 = (cP1[2] + cQ1[2]) * ez3;   /* state m0 + 24 */                  \
        __nv_bfloat16* sd = reinterpret_cast<__nv_bfloat16*>(shp[DST]);      \
        sd[sbase]     = __float2bfloat16_rn(s0);                             \
        sd[sbase + 2] = __float2bfloat16_rn(s1);                             \
        sd[sbase + 4] = __float2bfloat16_rn(s2);                             \
        sd[sbase + 6] = __float2bfloat16_rn(s3);                             \
        unsigned mm = max(max(__float_as_uint(s0), __float_as_uint(s1)),     \
                          max(__float_as_uint(s2), __float_as_uint(s3)));    \
        mm = __reduce_max_sync(0xffffffffu, mm);                             \
        if (lane == 0) wmax[DST][warp] = mm;                                 \
        _Pragma("unroll")                                                    \
        for (int k = 0; k < 4; k++) {                                        \
            ey[k] = __expf(yA[k]);                                           \
            yA[k] = yB[k];                                                   \
            yB[k] = (yp < yend) ? yp[8 * k] : 0.0f;                          \
        }                                                                    \
        yp += KDIM;                                                          \
        __syncthreads();                                                     \
    }

    const int len2 = len & ~1;
    for (int t = 0; t < len2; t += 2) {
        STEP(0, 1)
        STEP(1, 0)
    }
    if (len & 1) {
        STEP(0, 1)
    }
#undef STEP

    // ---- final: out[b] = log(sum_i s_i) + eacc*ln2 ----
    // each state held by 4 lanes (tig duplicates) -> warp sum = 4x partial
    float e = (s0 + s1) + (s2 + s3);
    e += __shfl_xor_sync(0xffffffffu, e, 16);
    e += __shfl_xor_sync(0xffffffffu, e, 8);
    e += __shfl_xor_sync(0xffffffffu, e, 4);
    e += __shfl_xor_sync(0xffffffffu, e, 2);
    e += __shfl_xor_sync(0xffffffffu, e, 1);
    if (lane == 0) redf[warp] = e;
    __syncthreads();
    if (tid == 0) {
        float tot = ((redf[0] + redf[1]) + (redf[2] + redf[3])) * 0.25f;
        out[b] = logf(tot) + (float)((double)eacc * 0.6931471805599453);
    }
}

extern "C" void kernel_launch(void* const* d_in, const int* in_sizes, int n_in,
                              void* d_out, int out_size) {
    const float* y     = (const float*)d_in[0];   // (B, T, K) f32
    const float* mask  = (const float*)d_in[1];   // (B, T)    f32
    const float* trans = (const float*)d_in[2];   // (K, K)    f32
    float* out = (float*)d_out;                   // (B,)      f32

    const int B = out_size;                       // 64
    const int T = in_sizes[1] / B;                // 256

    crf_fwd_kernel<<<B, 128>>>(y, mask, trans, out, T);
}